// round 9
// baseline (speedup 1.0000x reference)
#include <cuda_runtime.h>
#include <cuda_bf16.h>
#include <cstdint>

// NanEuclidean: X[4096,1024] f32, Y[4096,1024] f32 (10% NaN) -> out[4096,4096] f32
//   d = sqrt( clip(XX.pY - 2 Xc.Yc + pX.YY, 0) / max(1, pX.pY) * 1024 ), NaN where pc==0
//
// Portable tensor-core path (target is plain sm_103 -> no tcgen05):
//   prep: bf16 component planes, pre-swizzled SW128 tile images in device scratch
//   gemm: cp.async 2-stage pipeline + ldmatrix + mma.sync m16n8k16 bf16,
//         dual fp32 accumulators (D and presence count), fused epilogue.
//   R9: intra-chunk software pipelining of ldmatrix fragments (12 phases/chunk,
//       double-buffered frags) to hide LDS latency at 2 warps/SMSP.

#define DDIM  1024
#define NKB   16            // K chunks of 64
#define TILEB 16384u        // one 128-row x 128-byte swizzled tile image
#define STAGEB (6u * TILEB) // A0 A1 A2 B0 B1 B2 = 96 KB
#define GSMEM  (2u * STAGEB + 1024u)

// 24 MB each: [row_block(32)][comp(3)][k_block(16)] 16KB swizzled tiles
__device__ __align__(1024) __nv_bfloat16 g_nanEuc_A[12582912ull];
__device__ __align__(1024) __nv_bfloat16 g_nanEuc_B[12582912ull];

// ---------------- helpers ----------------
__device__ __forceinline__ uint32_t smem_u32(const void* p) {
    uint32_t a;
    asm("{ .reg .u64 t; cvta.to.shared.u64 t, %1; cvt.u32.u64 %0, t; }" : "=r"(a) : "l"(p));
    return a;
}

__device__ __forceinline__ void cpasync16(uint32_t dst, const void* src) {
    asm volatile("cp.async.cg.shared.global [%0], [%1], 16;" :: "r"(dst), "l"(src) : "memory");
}

#define LDSM4(r0, r1, r2, r3, addr) \
    asm volatile("ldmatrix.sync.aligned.m8n8.x4.shared.b16 {%0,%1,%2,%3}, [%4];" \
        : "=r"(r0), "=r"(r1), "=r"(r2), "=r"(r3) : "r"(addr))

__device__ __forceinline__ void mma16816(float* c, const uint32_t* a, const uint32_t* b) {
    asm volatile(
        "mma.sync.aligned.m16n8k16.row.col.f32.bf16.bf16.f32 "
        "{%0,%1,%2,%3}, {%4,%5,%6,%7}, {%8,%9}, {%0,%1,%2,%3};"
        : "+f"(c[0]), "+f"(c[1]), "+f"(c[2]), "+f"(c[3])
        : "r"(a[0]), "r"(a[1]), "r"(a[2]), "r"(a[3]), "r"(b[0]), "r"(b[1]));
}

__device__ __forceinline__ bool nan_bits(float x) {
    return (__float_as_uint(x) & 0x7fffffffu) > 0x7f800000u;  // fast-math safe
}

// ---------------- Kernel 1: precompute swizzled bf16 component tiles ----------------
// A comps (from X): [XX, Xc, pX].  B comps (from Y): [pY, -2*Yc, YY].
__global__ void __launch_bounds__(256) nanEuc_prep(const float* __restrict__ X,
                                                   const float* __restrict__ Y) {
    const int is_b   = (int)(blockIdx.x >> 13);
    const float* src = is_b ? Y : X;
    unsigned idx  = (blockIdx.x & 8191u) * 256u + threadIdx.x;   // 4096 rows * 512 k-pairs
    unsigned lane = idx & 31u;            // k-pair within 64-wide k block
    unsigned kb   = (idx >> 5) & 15u;     // k block
    unsigned row  = idx >> 9;             // 0..4095
    const float2 v = *reinterpret_cast<const float2*>(src + (size_t)row * DDIM + kb * 64u + lane * 2u);
    bool  m0 = nan_bits(v.x), m1 = nan_bits(v.y);
    float a0 = m0 ? 0.f : v.x, a1 = m1 ? 0.f : v.y;
    float p0 = m0 ? 0.f : 1.f, p1 = m1 ? 0.f : 1.f;
    float c00, c01, c10, c11, c20, c21;
    if (!is_b) { c00 = a0 * a0; c01 = a1 * a1; c10 = a0;        c11 = a1;        c20 = p0;      c21 = p1; }
    else       { c00 = p0;      c01 = p1;      c10 = -2.f * a0; c11 = -2.f * a1; c20 = a0 * a0; c21 = a1 * a1; }
    unsigned rb = row >> 7, r = row & 127u;
    unsigned off = r * 128u + lane * 4u;          // byte offset inside 128x128B tile
    unsigned sw  = off ^ ((off >> 3) & 0x70u);    // SW128
    char* dst = reinterpret_cast<char*>(is_b ? g_nanEuc_B : g_nanEuc_A);
    size_t base = ((size_t)rb * 48u + kb) * 16384u;       // comp stride = 16*16384
    *reinterpret_cast<__nv_bfloat162*>(dst + base +           sw) = __floats2bfloat162_rn(c00, c01);
    *reinterpret_cast<__nv_bfloat162*>(dst + base + 262144u + sw) = __floats2bfloat162_rn(c10, c11);
    *reinterpret_cast<__nv_bfloat162*>(dst + base + 524288u + sw) = __floats2bfloat162_rn(c20, c21);
}

// ---------------- Kernel 2: mma.sync GEMM with dual accumulators ----------------
// 256 threads = 8 warps in 2x4; warp tile 64x32; CTA tile 128x128.
// 12-phase pipelined inner loop: phase p = kk*3+comp; prefetch p+1 while p's MMAs run.
__global__ void __launch_bounds__(256, 1) nanEuc_gemm(float* __restrict__ out) {
    extern __shared__ char smraw[];
    const uint32_t smbase = (smem_u32(smraw) + 1023u) & ~1023u;

    const int tid = threadIdx.x, lane = tid & 31, w = tid >> 5;
    const int wr = w >> 2, wc = w & 3;            // wr in 0..1, wc in 0..3
    const int cb = blockIdx.x, rb = blockIdx.y;

    const char* Ag = reinterpret_cast<const char*>(g_nanEuc_A);
    const char* Bg = reinterpret_cast<const char*>(g_nanEuc_B);

    float accD[4][4][4];
    float accP[4][4][4];
    #pragma unroll
    for (int mi = 0; mi < 4; mi++)
        #pragma unroll
        for (int ni = 0; ni < 4; ni++)
            #pragma unroll
            for (int q = 0; q < 4; q++) { accD[mi][ni][q] = 0.f; accP[mi][ni][q] = 0.f; }

    // ldmatrix lane address components.
    const uint32_t segA = (uint32_t)(lane >> 4) * 16u;
    const uint32_t segB = (uint32_t)((lane >> 3) & 1) * 16u;
    uint32_t rtermA[4], xorA[4], rtermB[2], xorB[2];
    #pragma unroll
    for (int mi = 0; mi < 4; mi++) {
        uint32_t rowA = wr * 64 + mi * 16 + (lane & 15);
        rtermA[mi] = rowA * 128u;  xorA[mi] = (rowA & 7u) * 16u;
    }
    #pragma unroll
    for (int nt = 0; nt < 2; nt++) {
        uint32_t rowB = wc * 32 + nt * 16 + (lane & 7) + ((lane >> 4) & 1) * 8;
        rtermB[nt] = rowB * 128u;  xorB[nt] = (rowB & 7u) * 16u;
    }

    // stage loader: 6 contiguous 16KB tiles; i-th 16B chunk: tile = i>>10
    auto load_stage = [&](int s, int c) {
        const uint32_t dst0 = smbase + (uint32_t)s * STAGEB;
        #pragma unroll
        for (int i = tid; i < (int)(STAGEB / 16u); i += 256) {
            int t = i >> 10;                 // 0..5
            int comp = (t < 3) ? t : t - 3;
            const char* src = (t < 3
                ? Ag + ((size_t)(rb * 3 + comp) * NKB + c) * TILEB
                : Bg + ((size_t)(cb * 3 + comp) * NKB + c) * TILEB)
                + (size_t)(i & 1023) * 16u;
            cpasync16(dst0 + (uint32_t)i * 16u, src);
        }
        asm volatile("cp.async.commit_group;" ::: "memory");
    };

    load_stage(0, 0);
    load_stage(1, 1);

    // double-buffered fragments
    uint32_t abuf[2][4][4], bbuf[2][4][2], bP[4][2];

    for (int c = 0; c < NKB; c++) {
        const int s = c & 1;
        if (c + 1 < NKB) asm volatile("cp.async.wait_group 1;" ::: "memory");
        else             asm volatile("cp.async.wait_group 0;" ::: "memory");
        __syncthreads();

        const uint32_t base = smbase + (uint32_t)s * STAGEB;

        // preload phase 0 (kk=0, comp=0)
        #pragma unroll
        for (int mi = 0; mi < 4; mi++)
            LDSM4(abuf[0][mi][0], abuf[0][mi][1], abuf[0][mi][2], abuf[0][mi][3],
                  base + 0u * TILEB + rtermA[mi] + ((0u + segA) ^ xorA[mi]));
        #pragma unroll
        for (int nt = 0; nt < 2; nt++)
            LDSM4(bbuf[0][2 * nt][0], bbuf[0][2 * nt][1], bbuf[0][2 * nt + 1][0], bbuf[0][2 * nt + 1][1],
                  base + 3u * TILEB + rtermB[nt] + ((0u + segB) ^ xorB[nt]));

        #pragma unroll
        for (int p = 0; p < 12; p++) {
            const int cur = p & 1, nxt = cur ^ 1;
            const int comp = p - (p / 3) * 3;          // p % 3

            // prefetch phase p+1 into the other buffer
            if (p < 11) {
                const int pn = p + 1;
                const int kkn = pn / 3, compn = pn - kkn * 3;
                const uint32_t kbA = (uint32_t)kkn * 32u + segA;
                const uint32_t kbB = (uint32_t)kkn * 32u + segB;
                #pragma unroll
                for (int mi = 0; mi < 4; mi++)
                    LDSM4(abuf[nxt][mi][0], abuf[nxt][mi][1], abuf[nxt][mi][2], abuf[nxt][mi][3],
                          base + (uint32_t)compn * TILEB + rtermA[mi] + (kbA ^ xorA[mi]));
                #pragma unroll
                for (int nt = 0; nt < 2; nt++)
                    LDSM4(bbuf[nxt][2 * nt][0], bbuf[nxt][2 * nt][1],
                          bbuf[nxt][2 * nt + 1][0], bbuf[nxt][2 * nt + 1][1],
                          base + (uint32_t)(3 + compn) * TILEB + rtermB[nt] + (kbB ^ xorB[nt]));
            }

            // comp0: keep the pY fragments for the PC mma at comp2 of the same kk
            if (comp == 0) {
                #pragma unroll
                for (int ni = 0; ni < 4; ni++) { bP[ni][0] = bbuf[cur][ni][0]; bP[ni][1] = bbuf[cur][ni][1]; }
            }

            // MMAs for phase p
            if (comp != 2) {
                #pragma unroll
                for (int mi = 0; mi < 4; mi++)
                    #pragma unroll
                    for (int ni = 0; ni < 4; ni++)
                        mma16816(accD[mi][ni], abuf[cur][mi], bbuf[cur][ni]);
            } else {
                #pragma unroll
                for (int mi = 0; mi < 4; mi++)
                    #pragma unroll
                    for (int ni = 0; ni < 4; ni++) {
                        mma16816(accD[mi][ni], abuf[cur][mi], bbuf[cur][ni]);
                        mma16816(accP[mi][ni], abuf[cur][mi], bP[ni]);
                    }
            }
        }
        __syncthreads();
        if (c + 2 < NKB) load_stage(s, c + 2);
    }

    // ---- epilogue: r = pc==0 ? NaN : sqrt(max(d,0) * 1024 / max(pc,1)) ----
    const int r0 = rb * 128 + wr * 64 + (lane >> 2);
    const int c0 = cb * 128 + wc * 32 + (lane & 3) * 2;
    #pragma unroll
    for (int mi = 0; mi < 4; mi++)
        #pragma unroll
        for (int ni = 0; ni < 4; ni++) {
            const int rr = r0 + mi * 16;
            const int cc = c0 + ni * 8;
            float v[4];
            #pragma unroll
            for (int q = 0; q < 4; q++) {
                float d = accD[mi][ni][q], p = accP[mi][ni][q];
                v[q] = (p == 0.f) ? __int_as_float(0x7fc00000)
                                  : sqrtf(fmaxf(d, 0.f) * 1024.f / fmaxf(p, 1.f));
            }
            *reinterpret_cast<float2*>(out + (size_t)rr * 4096u + cc)       = make_float2(v[0], v[1]);
            *reinterpret_cast<float2*>(out + (size_t)(rr + 8) * 4096u + cc) = make_float2(v[2], v[3]);
        }
}

// ---------------- launch ----------------
extern "C" void kernel_launch(void* const* d_in, const int* in_sizes, int n_in,
                              void* d_out, int out_size) {
    (void)in_sizes; (void)n_in; (void)out_size;
    const float* X = (const float*)d_in[0];
    const float* Y = (const float*)d_in[1];
    float* out = (float*)d_out;

    nanEuc_prep<<<16384, 256>>>(X, Y);

    cudaFuncSetAttribute(nanEuc_gemm, cudaFuncAttributeMaxDynamicSharedMemorySize, GSMEM);
    nanEuc_gemm<<<dim3(32, 32, 1), 256, GSMEM>>>(out);
}

// round 11
// speedup vs baseline: 1.5512x; 1.5512x over previous
#include <cuda_runtime.h>
#include <cuda_bf16.h>
#include <cstdint>
#include <cstring>

// NanEuclidean: X[4096,1024] f32, Y[4096,1024] f32 (10% NaN) -> out[4096,4096] f32
//   d = sqrt( clip(XX.pY - 2 Xc.Yc + pX.YY, 0) / max(1, pX.pY) * 1024 ), NaN where pc==0
//
// R11 = R10 with the missing intrinsic replaced by a bit-cast helper.
// R10: R6 compute config (512 thr, 16 warps 4x4, warp tile 32x32) + 4-stage
//      K32 pipeline with ONE __syncthreads per chunk. Tiles are 128 rows x 64B
//      with per-row XOR swizzle (seg ^ (row>>1)&3) -> conflict-free ldmatrix.

#define DDIM   1024
#define NKB    32            // K chunks of 32
#define TILE8K 8192u         // one 128-row x 64-byte swizzled tile image
#define STAGEB (6u * TILE8K) // A0 A1 A2 B0 B1 B2 = 48 KB
#define NSTAGE 4
#define GSMEM  (NSTAGE * STAGEB + 1024u)

// 24 MB each: [row_block(32)][comp(3)][k_block(32)] 8KB tiles
__device__ __align__(1024) __nv_bfloat16 g_nanEuc_A[12582912ull];
__device__ __align__(1024) __nv_bfloat16 g_nanEuc_B[12582912ull];

// ---------------- helpers ----------------
__device__ __forceinline__ uint32_t bf2_u32(__nv_bfloat162 v) {
    uint32_t u;
    memcpy(&u, &v, 4);
    return u;
}

__device__ __forceinline__ uint32_t smem_u32(const void* p) {
    uint32_t a;
    asm("{ .reg .u64 t; cvta.to.shared.u64 t, %1; cvt.u32.u64 %0, t; }" : "=r"(a) : "l"(p));
    return a;
}

__device__ __forceinline__ void cpasync16(uint32_t dst, const void* src) {
    asm volatile("cp.async.cg.shared.global [%0], [%1], 16;" :: "r"(dst), "l"(src) : "memory");
}

#define LDSM4(r0, r1, r2, r3, addr) \
    asm volatile("ldmatrix.sync.aligned.m8n8.x4.shared.b16 {%0,%1,%2,%3}, [%4];" \
        : "=r"(r0), "=r"(r1), "=r"(r2), "=r"(r3) : "r"(addr))

__device__ __forceinline__ void mma16816(float* c, const uint32_t* a, const uint32_t* b) {
    asm volatile(
        "mma.sync.aligned.m16n8k16.row.col.f32.bf16.bf16.f32 "
        "{%0,%1,%2,%3}, {%4,%5,%6,%7}, {%8,%9}, {%0,%1,%2,%3};"
        : "+f"(c[0]), "+f"(c[1]), "+f"(c[2]), "+f"(c[3])
        : "r"(a[0]), "r"(a[1]), "r"(a[2]), "r"(a[3]), "r"(b[0]), "r"(b[1]));
}

__device__ __forceinline__ bool nan_bits(float x) {
    return (__float_as_uint(x) & 0x7fffffffu) > 0x7f800000u;  // fast-math safe
}

// ---------------- Kernel 1: precompute swizzled bf16 component tiles ----------------
// A comps (from X): [XX, Xc, pX].  B comps (from Y): [pY, -2*Yc, YY].
// Tile: 128 rows x 64B (32 bf16). 16B seg s stored at local seg s ^ ((r>>1)&3).
__global__ void __launch_bounds__(256) nanEuc_prep(const float* __restrict__ X,
                                                   const float* __restrict__ Y) {
    const int is_b   = (int)(blockIdx.x >> 11);       // 2048 blocks per matrix
    const float* src = is_b ? Y : X;
    unsigned idx = (blockIdx.x & 2047u) * 256u + threadIdx.x;  // 0..524287
    unsigned s   = idx & 3u;              // 16B seg within 64B (8 bf16 = 8 f32 in)
    unsigned kb  = (idx >> 2) & 31u;      // k block of 32
    unsigned row = idx >> 7;              // 0..4095

    const float4 v0 = *reinterpret_cast<const float4*>(src + (size_t)row * DDIM + kb * 32u + s * 8u);
    const float4 v1 = *reinterpret_cast<const float4*>(src + (size_t)row * DDIM + kb * 32u + s * 8u + 4u);
    float x[8] = {v0.x, v0.y, v0.z, v0.w, v1.x, v1.y, v1.z, v1.w};

    uint32_t c0[4], c1[4], c2[4];         // 4 bf16x2 per comp
    #pragma unroll
    for (int i = 0; i < 4; i++) {
        float e0 = x[2 * i], e1 = x[2 * i + 1];
        bool  m0 = nan_bits(e0), m1 = nan_bits(e1);
        float a0 = m0 ? 0.f : e0, a1 = m1 ? 0.f : e1;
        float p0 = m0 ? 0.f : 1.f, p1 = m1 ? 0.f : 1.f;
        float q0 = a0 * a0, q1 = a1 * a1;
        if (!is_b) {
            c0[i] = bf2_u32(__floats2bfloat162_rn(q0, q1));                 // XX
            c1[i] = bf2_u32(__floats2bfloat162_rn(a0, a1));                 // Xc
            c2[i] = bf2_u32(__floats2bfloat162_rn(p0, p1));                 // pX
        } else {
            c0[i] = bf2_u32(__floats2bfloat162_rn(p0, p1));                 // pY
            c1[i] = bf2_u32(__floats2bfloat162_rn(-2.f * a0, -2.f * a1));   // -2Yc
            c2[i] = bf2_u32(__floats2bfloat162_rn(q0, q1));                 // YY
        }
    }

    unsigned rb = row >> 7, r = row & 127u;
    unsigned off = r * 64u + ((s ^ ((r >> 1) & 3u)) << 4);   // swizzled 16B slot
    char* dst = reinterpret_cast<char*>(is_b ? g_nanEuc_B : g_nanEuc_A);
    size_t tb = ((size_t)rb * 96u + kb) * 8192u;             // [rb][comp][kb] tiles; comp stride 32*8192
    *reinterpret_cast<uint4*>(dst + tb +           off) = make_uint4(c0[0], c0[1], c0[2], c0[3]);
    *reinterpret_cast<uint4*>(dst + tb + 262144u + off) = make_uint4(c1[0], c1[1], c1[2], c1[3]);
    *reinterpret_cast<uint4*>(dst + tb + 524288u + off) = make_uint4(c2[0], c2[1], c2[2], c2[3]);
}

// ---------------- Kernel 2: mma.sync GEMM with dual accumulators ----------------
// 512 threads = 16 warps in 4x4; warp tile 32x32; CTA tile 128x128.
// 4-stage K32 pipeline, one __syncthreads per chunk, loads issued before compute.
__global__ void __launch_bounds__(512, 1) nanEuc_gemm(float* __restrict__ out) {
    extern __shared__ char smraw[];
    const uint32_t smbase = (smem_u32(smraw) + 1023u) & ~1023u;

    const int tid = threadIdx.x, lane = tid & 31, w = tid >> 5;
    const int wr = w >> 2, wc = w & 3;
    const int cb = blockIdx.x, rb = blockIdx.y;

    const char* Ag = reinterpret_cast<const char*>(g_nanEuc_A);
    const char* Bg = reinterpret_cast<const char*>(g_nanEuc_B);

    float accD[2][4][4];
    float accP[2][4][4];
    #pragma unroll
    for (int mi = 0; mi < 2; mi++)
        #pragma unroll
        for (int ni = 0; ni < 4; ni++)
            #pragma unroll
            for (int q = 0; q < 4; q++) { accD[mi][ni][q] = 0.f; accP[mi][ni][q] = 0.f; }

    // ldmatrix lane addressing (64B rows, seg swizzle s^((row>>1)&3))
    const uint32_t hiA = (uint32_t)(lane >> 4);        // 0/1 -> k16 half
    const uint32_t hiB = (uint32_t)((lane >> 3) & 1);
    uint32_t rtermA[2], xorA[2], rtermB[2], xorB[2];
    #pragma unroll
    for (int mi = 0; mi < 2; mi++) {
        uint32_t rowA = wr * 32 + mi * 16 + (lane & 15);
        rtermA[mi] = rowA * 64u;  xorA[mi] = (rowA >> 1) & 3u;
    }
    #pragma unroll
    for (int nt = 0; nt < 2; nt++) {
        uint32_t rowB = wc * 32 + nt * 16 + (lane & 7) + ((lane >> 4) & 1) * 8;
        rtermB[nt] = rowB * 64u;  xorB[nt] = (rowB >> 1) & 3u;
    }

    // stage loader: 6 contiguous 8KB tiles; i-th 16B chunk: tile = i>>9
    auto load_stage = [&](int slot, int c) {
        const uint32_t dst0 = smbase + (uint32_t)slot * STAGEB;
        #pragma unroll
        for (int i = tid; i < (int)(STAGEB / 16u); i += 512) {
            int t = i >> 9;                  // 0..5
            int comp = (t < 3) ? t : t - 3;
            const char* src = (t < 3
                ? Ag + ((size_t)(rb * 3 + comp) * NKB + c) * TILE8K
                : Bg + ((size_t)(cb * 3 + comp) * NKB + c) * TILE8K)
                + (size_t)(i & 511) * 16u;
            cpasync16(dst0 + (uint32_t)i * 16u, src);
        }
    };

    // prologue: stages 0..2 in flight
    #pragma unroll
    for (int c = 0; c < NSTAGE - 1; c++) {
        load_stage(c, c);
        asm volatile("cp.async.commit_group;" ::: "memory");
    }

    for (int c = 0; c < NKB; c++) {
        asm volatile("cp.async.wait_group %0;" :: "n"(NSTAGE - 2) : "memory");
        __syncthreads();

        // issue next load immediately (into slot consumed at iteration c-1)
        if (c + NSTAGE - 1 < NKB) load_stage((c + NSTAGE - 1) & (NSTAGE - 1), c + NSTAGE - 1);
        asm volatile("cp.async.commit_group;" ::: "memory");   // empty group OK -> keeps count

        const uint32_t base = smbase + (uint32_t)(c & (NSTAGE - 1)) * STAGEB;
        #pragma unroll
        for (int kk = 0; kk < 2; kk++) {
            const uint32_t sA = (uint32_t)kk * 2u + hiA;   // logical 16B seg 0..3
            const uint32_t sB = (uint32_t)kk * 2u + hiB;
            uint32_t a[2][4], b[4][2], bP[4][2];

            // ---- comp 0: D += XX . pY^T ; save pY frags for PC ----
            #pragma unroll
            for (int mi = 0; mi < 2; mi++)
                LDSM4(a[mi][0], a[mi][1], a[mi][2], a[mi][3],
                      base + 0u * TILE8K + rtermA[mi] + ((sA ^ xorA[mi]) << 4));
            #pragma unroll
            for (int nt = 0; nt < 2; nt++)
                LDSM4(b[2 * nt][0], b[2 * nt][1], b[2 * nt + 1][0], b[2 * nt + 1][1],
                      base + 3u * TILE8K + rtermB[nt] + ((sB ^ xorB[nt]) << 4));
            #pragma unroll
            for (int ni = 0; ni < 4; ni++) { bP[ni][0] = b[ni][0]; bP[ni][1] = b[ni][1]; }
            #pragma unroll
            for (int mi = 0; mi < 2; mi++)
                #pragma unroll
                for (int ni = 0; ni < 4; ni++) mma16816(accD[mi][ni], a[mi], b[ni]);

            // ---- comp 1: D += Xc . (-2 Yc)^T ----
            #pragma unroll
            for (int mi = 0; mi < 2; mi++)
                LDSM4(a[mi][0], a[mi][1], a[mi][2], a[mi][3],
                      base + 1u * TILE8K + rtermA[mi] + ((sA ^ xorA[mi]) << 4));
            #pragma unroll
            for (int nt = 0; nt < 2; nt++)
                LDSM4(b[2 * nt][0], b[2 * nt][1], b[2 * nt + 1][0], b[2 * nt + 1][1],
                      base + 4u * TILE8K + rtermB[nt] + ((sB ^ xorB[nt]) << 4));
            #pragma unroll
            for (int mi = 0; mi < 2; mi++)
                #pragma unroll
                for (int ni = 0; ni < 4; ni++) mma16816(accD[mi][ni], a[mi], b[ni]);

            // ---- comp 2: D += pX . YY^T ; PC += pX . pY^T (reuses bP) ----
            #pragma unroll
            for (int mi = 0; mi < 2; mi++)
                LDSM4(a[mi][0], a[mi][1], a[mi][2], a[mi][3],
                      base + 2u * TILE8K + rtermA[mi] + ((sA ^ xorA[mi]) << 4));
            #pragma unroll
            for (int nt = 0; nt < 2; nt++)
                LDSM4(b[2 * nt][0], b[2 * nt][1], b[2 * nt + 1][0], b[2 * nt + 1][1],
                      base + 5u * TILE8K + rtermB[nt] + ((sB ^ xorB[nt]) << 4));
            #pragma unroll
            for (int mi = 0; mi < 2; mi++)
                #pragma unroll
                for (int ni = 0; ni < 4; ni++) {
                    mma16816(accD[mi][ni], a[mi], b[ni]);
                    mma16816(accP[mi][ni], a[mi], bP[ni]);
                }
        }
    }

    // ---- epilogue: r = pc==0 ? NaN : sqrt(max(d,0) * 1024 / max(pc,1)) ----
    const int r0 = rb * 128 + wr * 32 + (lane >> 2);
    const int c0 = cb * 128 + wc * 32 + (lane & 3) * 2;
    #pragma unroll
    for (int mi = 0; mi < 2; mi++)
        #pragma unroll
        for (int ni = 0; ni < 4; ni++) {
            const int rr = r0 + mi * 16;
            const int cc = c0 + ni * 8;
            float v[4];
            #pragma unroll
            for (int q = 0; q < 4; q++) {
                float d = accD[mi][ni][q], p = accP[mi][ni][q];
                v[q] = (p == 0.f) ? __int_as_float(0x7fc00000)
                                  : sqrtf(fmaxf(d, 0.f) * 1024.f / fmaxf(p, 1.f));
            }
            *reinterpret_cast<float2*>(out + (size_t)rr * 4096u + cc)       = make_float2(v[0], v[1]);
            *reinterpret_cast<float2*>(out + (size_t)(rr + 8) * 4096u + cc) = make_float2(v[2], v[3]);
        }
}

// ---------------- launch ----------------
extern "C" void kernel_launch(void* const* d_in, const int* in_sizes, int n_in,
                              void* d_out, int out_size) {
    (void)in_sizes; (void)n_in; (void)out_size;
    const float* X = (const float*)d_in[0];
    const float* Y = (const float*)d_in[1];
    float* out = (float*)d_out;

    nanEuc_prep<<<4096, 256>>>(X, Y);

    cudaFuncSetAttribute(nanEuc_gemm, cudaFuncAttributeMaxDynamicSharedMemorySize, GSMEM);
    nanEuc_gemm<<<dim3(32, 32, 1), 512, GSMEM>>>(out);
}